// round 8
// baseline (speedup 1.0000x reference)
#include <cuda_runtime.h>
#include <cuda_fp16.h>
#include <math.h>

#define N_NODES 100000
#define E_EDGES 1600000
#define E2      (E_EDGES + N_NODES)   // 1,700,000
#define IN_C    128
#define HID     64
#define HEADS   4
#define HH      (HEADS * HID)         // 256
#define OUT_C   2
#define NEG_SLOPE 0.2f
#define SCAN_T  1024

struct Edge { int src; float norm; };

// ---------------- scratch ----------------------------------------------------
__device__ __align__(16) int    g_degi[N_NODES];
__device__ __align__(16) int    g_cnt[N_NODES];
__device__ __align__(16) int    g_rowptr[N_NODES + 1];
__device__ __align__(16) float  g_dinv[N_NODES];
__device__ __align__(16) Edge   g_csr[E2];
__device__ __align__(16) __half g_xw1h[(size_t)N_NODES * HID];
__device__ __align__(16) float  g_h0 [(size_t)N_NODES * HID];
__device__ __align__(16) __half g_xw2h[(size_t)N_NODES * HH];    // 51MB, L2-resident
__device__ __align__(16) float  g_as [(size_t)N_NODES * HEADS];
__device__ __align__(16) float  g_ad [(size_t)N_NODES * HEADS];
__device__ __align__(16) float  g_mx[8];
__device__ __align__(16) float  g_hw3[(size_t)N_NODES * OUT_C];

__device__ __forceinline__ float lrelu(float x) { return x > 0.0f ? x : NEG_SLOPE * x; }

__device__ __forceinline__ void atomicMaxFloat(float* addr, float value) {
    if (value >= 0.0f) atomicMax((int*)addr, __float_as_int(value));
    else               atomicMin((unsigned int*)addr, __float_as_uint(value));
}

// ---------------- CSR build --------------------------------------------------
__global__ void k_init() {
    int i = blockIdx.x * blockDim.x + threadIdx.x;
    if (i < N_NODES) { g_degi[i] = 0; g_cnt[i] = 0; }
    if (i < 8) g_mx[i] = -3.402823466e38f;
}

__global__ void k_edges(const int* __restrict__ ei) {
    int e = blockIdx.x * blockDim.x + threadIdx.x;
    if (e >= E2) return;
    int d = (e < E_EDGES) ? ei[E_EDGES + e] : (e - E_EDGES);
    atomicAdd(&g_degi[d], 1);
}

__global__ void k_scan() {
    __shared__ int part[SCAN_T];
    const int CH = (N_NODES + SCAN_T - 1) / SCAN_T;
    int t = threadIdx.x;
    int base = t * CH;
    int hi = min(base + CH, N_NODES);
    int sum = 0;
    for (int i = base; i < hi; i++) sum += g_degi[i];
    part[t] = sum;
    __syncthreads();
    for (int off = 1; off < SCAN_T; off <<= 1) {
        int v = (t >= off) ? part[t - off] : 0;
        __syncthreads();
        part[t] += v;
        __syncthreads();
    }
    int run = (t == 0) ? 0 : part[t - 1];
    for (int i = base; i < hi; i++) {
        g_rowptr[i] = run;
        int dg = g_degi[i];
        g_dinv[i] = dg > 0 ? rsqrtf((float)dg) : 0.0f;
        run += dg;
    }
    if (t == SCAN_T - 1) g_rowptr[N_NODES] = run;
}

__global__ void k_fill(const int* __restrict__ ei) {
    int e = blockIdx.x * blockDim.x + threadIdx.x;
    if (e >= E2) return;
    int s, d;
    if (e < E_EDGES) { s = ei[e]; d = ei[E_EDGES + e]; }
    else             { s = e - E_EDGES; d = s; }
    int pos = g_rowptr[d] + atomicAdd(&g_cnt[d], 1);
    Edge ed; ed.src = s; ed.norm = g_dinv[s] * g_dinv[d];
    g_csr[pos] = ed;
}

// ---------------- GEMM 1: xw1h = fp16(x @ W1)   64x64 tile, 4x4/thread -----
__global__ void __launch_bounds__(256) k_gemm1(const float* __restrict__ x,
                                               const float* __restrict__ W1) {
    __shared__ __align__(16) float As[64][68];
    __shared__ __align__(16) float Bs[64][HID];
    int tid = threadIdx.x;
    int tx = tid & 15, ty = tid >> 4;
    int row0 = blockIdx.x * 64;
    float acc[4][4];
    #pragma unroll
    for (int i = 0; i < 4; i++)
        #pragma unroll
        for (int j = 0; j < 4; j++) acc[i][j] = 0.0f;

    for (int kc = 0; kc < IN_C; kc += 64) {
        __syncthreads();
        #pragma unroll
        for (int it = 0; it < 4; it++) {
            int idx = tid + it * 256;
            int r = idx >> 4, k4 = idx & 15;
            int row = row0 + r;
            float4 v = make_float4(0.f, 0.f, 0.f, 0.f);
            if (row < N_NODES)
                v = *(const float4*)&x[(size_t)row * IN_C + kc + k4 * 4];
            *(float4*)&As[r][k4 * 4] = v;
        }
        #pragma unroll
        for (int it = 0; it < 4; it++) {
            int idx = tid + it * 256;
            int k = idx >> 4, c4 = idx & 15;
            *(float4*)&Bs[k][c4 * 4] = *(const float4*)&W1[(size_t)(kc + k) * HID + c4 * 4];
        }
        __syncthreads();
        #pragma unroll 16
        for (int k = 0; k < 64; k++) {
            float a0 = As[ty * 4 + 0][k], a1 = As[ty * 4 + 1][k];
            float a2 = As[ty * 4 + 2][k], a3 = As[ty * 4 + 3][k];
            float4 b = *(const float4*)&Bs[k][tx * 4];
            acc[0][0] += a0 * b.x; acc[0][1] += a0 * b.y; acc[0][2] += a0 * b.z; acc[0][3] += a0 * b.w;
            acc[1][0] += a1 * b.x; acc[1][1] += a1 * b.y; acc[1][2] += a1 * b.z; acc[1][3] += a1 * b.w;
            acc[2][0] += a2 * b.x; acc[2][1] += a2 * b.y; acc[2][2] += a2 * b.z; acc[2][3] += a2 * b.w;
            acc[3][0] += a3 * b.x; acc[3][1] += a3 * b.y; acc[3][2] += a3 * b.z; acc[3][3] += a3 * b.w;
        }
    }
    #pragma unroll
    for (int i = 0; i < 4; i++) {
        int row = row0 + ty * 4 + i;
        if (row < N_NODES) {
            __half2 p0 = __floats2half2_rn(acc[i][0], acc[i][1]);
            __half2 p1 = __floats2half2_rn(acc[i][2], acc[i][3]);
            uint2 u; u.x = *(unsigned*)&p0; u.y = *(unsigned*)&p1;
            *(uint2*)&g_xw1h[(size_t)row * HID + tx * 4] = u;
        }
    }
}

// ---------------- GCN-1 gather (fp16, 8-unroll) ----------------------------
__global__ void k_gcn1(const float* __restrict__ b1) {
    int warp = (blockIdx.x * blockDim.x + threadIdx.x) >> 5;
    int lane = threadIdx.x & 31;
    if (warp >= N_NODES) return;
    int r0 = g_rowptr[warp], r1 = g_rowptr[warp + 1];
    float acc0 = 0.0f, acc1 = 0.0f;
    int off = lane * 2;
    int e = r0;
    for (; e + 8 <= r1; e += 8) {
        Edge ed[8];
        #pragma unroll
        for (int j = 0; j < 8; j++) ed[j] = g_csr[e + j];
        __half2 hv[8];
        #pragma unroll
        for (int j = 0; j < 8; j++)
            hv[j] = *(const __half2*)&g_xw1h[(size_t)ed[j].src * HID + off];
        #pragma unroll
        for (int j = 0; j < 8; j++) {
            float2 v = __half22float2(hv[j]);
            acc0 += v.x * ed[j].norm; acc1 += v.y * ed[j].norm;
        }
    }
    for (; e < r1; e++) {
        Edge ed = g_csr[e];
        float2 v = __half22float2(*(const __half2*)&g_xw1h[(size_t)ed.src * HID + off]);
        acc0 += v.x * ed.norm; acc1 += v.y * ed.norm;
    }
    float2 o;
    o.x = fmaxf(acc0 + __ldg(&b1[off]),     0.0f);
    o.y = fmaxf(acc1 + __ldg(&b1[off + 1]), 0.0f);
    *(float2*)&g_h0[(size_t)warp * HID + off] = o;
}

// ---------------- GEMM 2: xw2h = fp16(h0 @ W2), + attention dots -----------
__global__ void __launch_bounds__(256) k_gemm2(const float* __restrict__ W2,
                                               const float* __restrict__ attS,
                                               const float* __restrict__ attD) {
    __shared__ __align__(16) float As[64][68];
    __shared__ __align__(16) float Bs[64][64];
    __shared__ float sa[64], sd[64];
    int tid = threadIdx.x;
    int tx = tid & 15, ty = tid >> 4;
    int head = blockIdx.y;
    int row0 = blockIdx.x * 64;

    #pragma unroll
    for (int it = 0; it < 4; it++) {
        int idx = tid + it * 256;
        int r = idx >> 4, k4 = idx & 15;
        int row = row0 + r;
        float4 v = make_float4(0.f, 0.f, 0.f, 0.f);
        if (row < N_NODES)
            v = *(const float4*)&g_h0[(size_t)row * HID + k4 * 4];
        *(float4*)&As[r][k4 * 4] = v;
    }
    #pragma unroll
    for (int it = 0; it < 4; it++) {
        int idx = tid + it * 256;
        int k = idx >> 4, c4 = idx & 15;
        *(float4*)&Bs[k][c4 * 4] =
            *(const float4*)&W2[(size_t)k * HH + head * 64 + c4 * 4];
    }
    if (tid < 64) { sa[tid] = attS[head * 64 + tid]; sd[tid] = attD[head * 64 + tid]; }
    __syncthreads();

    float acc[4][4];
    #pragma unroll
    for (int i = 0; i < 4; i++)
        #pragma unroll
        for (int j = 0; j < 4; j++) acc[i][j] = 0.0f;

    #pragma unroll 16
    for (int k = 0; k < 64; k++) {
        float a0 = As[ty * 4 + 0][k], a1 = As[ty * 4 + 1][k];
        float a2 = As[ty * 4 + 2][k], a3 = As[ty * 4 + 3][k];
        float4 b = *(const float4*)&Bs[k][tx * 4];
        acc[0][0] += a0 * b.x; acc[0][1] += a0 * b.y; acc[0][2] += a0 * b.z; acc[0][3] += a0 * b.w;
        acc[1][0] += a1 * b.x; acc[1][1] += a1 * b.y; acc[1][2] += a1 * b.z; acc[1][3] += a1 * b.w;
        acc[2][0] += a2 * b.x; acc[2][1] += a2 * b.y; acc[2][2] += a2 * b.z; acc[2][3] += a2 * b.w;
        acc[3][0] += a3 * b.x; acc[3][1] += a3 * b.y; acc[3][2] += a3 * b.z; acc[3][3] += a3 * b.w;
    }

    #pragma unroll
    for (int i = 0; i < 4; i++) {
        int row = row0 + ty * 4 + i;
        if (row < N_NODES) {
            __half2 p0 = __floats2half2_rn(acc[i][0], acc[i][1]);
            __half2 p1 = __floats2half2_rn(acc[i][2], acc[i][3]);
            uint2 u; u.x = *(unsigned*)&p0; u.y = *(unsigned*)&p1;
            *(uint2*)&g_xw2h[(size_t)row * HH + head * 64 + tx * 4] = u;
        }
    }

    float ps[4], pd[4];
    #pragma unroll
    for (int i = 0; i < 4; i++) {
        float s = 0.f, d = 0.f;
        #pragma unroll
        for (int j = 0; j < 4; j++) {
            s += acc[i][j] * sa[tx * 4 + j];
            d += acc[i][j] * sd[tx * 4 + j];
        }
        ps[i] = s; pd[i] = d;
    }
    #pragma unroll
    for (int off = 8; off >= 1; off >>= 1) {
        #pragma unroll
        for (int i = 0; i < 4; i++) {
            ps[i] += __shfl_xor_sync(0xffffffffu, ps[i], off);
            pd[i] += __shfl_xor_sync(0xffffffffu, pd[i], off);
        }
    }
    if (tx == 0) {
        #pragma unroll
        for (int i = 0; i < 4; i++) {
            int row = row0 + ty * 4 + i;
            if (row < N_NODES) {
                g_as[(size_t)row * HEADS + head] = ps[i];
                g_ad[(size_t)row * HEADS + head] = pd[i];
            }
        }
    }
}

// ---------------- global per-head max of a_s / a_d -------------------------
__global__ void k_maxred() {
    int i = blockIdx.x * blockDim.x + threadIdx.x;
    int lane = threadIdx.x & 31;
    float4 a = make_float4(-3.4e38f, -3.4e38f, -3.4e38f, -3.4e38f);
    float4 d = a;
    if (i < N_NODES) {
        a = *(const float4*)&g_as[(size_t)i * HEADS];
        d = *(const float4*)&g_ad[(size_t)i * HEADS];
    }
    #pragma unroll
    for (int o = 16; o >= 1; o >>= 1) {
        a.x = fmaxf(a.x, __shfl_xor_sync(0xffffffffu, a.x, o));
        a.y = fmaxf(a.y, __shfl_xor_sync(0xffffffffu, a.y, o));
        a.z = fmaxf(a.z, __shfl_xor_sync(0xffffffffu, a.z, o));
        a.w = fmaxf(a.w, __shfl_xor_sync(0xffffffffu, a.w, o));
        d.x = fmaxf(d.x, __shfl_xor_sync(0xffffffffu, d.x, o));
        d.y = fmaxf(d.y, __shfl_xor_sync(0xffffffffu, d.y, o));
        d.z = fmaxf(d.z, __shfl_xor_sync(0xffffffffu, d.z, o));
        d.w = fmaxf(d.w, __shfl_xor_sync(0xffffffffu, d.w, o));
    }
    if (lane == 0) {
        atomicMaxFloat(&g_mx[0], a.x); atomicMaxFloat(&g_mx[1], a.y);
        atomicMaxFloat(&g_mx[2], a.z); atomicMaxFloat(&g_mx[3], a.w);
        atomicMaxFloat(&g_mx[4], d.x); atomicMaxFloat(&g_mx[5], d.y);
        atomicMaxFloat(&g_mx[6], d.z); atomicMaxFloat(&g_mx[7], d.w);
    }
}

// ---------------- fused GAT: 4 warps per node (warp = head) ----------------
// block = 256 = 8 warps = 2 nodes; grid = 50000 exact.
__global__ void __launch_bounds__(256) k_gat(const float* __restrict__ b2,
                                             const float* __restrict__ W3) {
    __shared__ float sW3[HH * 2];
    __shared__ float sb2[HH];
    __shared__ float sC[HEADS];
    __shared__ float sPart[8][2];
    int tid = threadIdx.x;
    sW3[tid * 2]     = W3[tid * 2];
    sW3[tid * 2 + 1] = W3[tid * 2 + 1];
    sb2[tid]         = b2[tid];
    if (tid < HEADS) sC[tid] = lrelu(g_mx[tid] + g_mx[tid + 4]);
    __syncthreads();

    int wl   = tid >> 5;                         // 0..7
    int node = blockIdx.x * 2 + (wl >> 2);
    int head = wl & 3;
    int lane = tid & 31;
    int r0 = g_rowptr[node], r1 = g_rowptr[node + 1];

    int col  = head * 64 + lane * 2;             // 2 fp16 channels per lane
    float adh = g_ad[(size_t)node * HEADS + head];
    float Ch  = sC[head];

    float acc0 = 0.0f, acc1 = 0.0f, den = 0.0f;

    int e = r0;
    for (; e + 4 <= r1; e += 4) {
        int s0 = g_csr[e].src,     s1 = g_csr[e + 1].src;
        int s2 = g_csr[e + 2].src, s3 = g_csr[e + 3].src;
        float as0 = g_as[(size_t)s0 * HEADS + head];
        float as1 = g_as[(size_t)s1 * HEADS + head];
        float as2 = g_as[(size_t)s2 * HEADS + head];
        float as3 = g_as[(size_t)s3 * HEADS + head];
        __half2 h0 = *(const __half2*)&g_xw2h[(size_t)s0 * HH + col];
        __half2 h1 = *(const __half2*)&g_xw2h[(size_t)s1 * HH + col];
        __half2 h2 = *(const __half2*)&g_xw2h[(size_t)s2 * HH + col];
        __half2 h3 = *(const __half2*)&g_xw2h[(size_t)s3 * HH + col];
        float w0 = __expf(lrelu(as0 + adh) - Ch);
        float w1 = __expf(lrelu(as1 + adh) - Ch);
        float w2 = __expf(lrelu(as2 + adh) - Ch);
        float w3 = __expf(lrelu(as3 + adh) - Ch);
        den += (w0 + w1) + (w2 + w3);
        float2 f;
        f = __half22float2(h0); acc0 += f.x * w0; acc1 += f.y * w0;
        f = __half22float2(h1); acc0 += f.x * w1; acc1 += f.y * w1;
        f = __half22float2(h2); acc0 += f.x * w2; acc1 += f.y * w2;
        f = __half22float2(h3); acc0 += f.x * w3; acc1 += f.y * w3;
    }
    for (; e < r1; e++) {
        int s = g_csr[e].src;
        float ash = g_as[(size_t)s * HEADS + head];
        float w = __expf(lrelu(ash + adh) - Ch);
        den += w;
        float2 f = __half22float2(*(const __half2*)&g_xw2h[(size_t)s * HH + col]);
        acc0 += f.x * w; acc1 += f.y * w;
    }
    float inv = 1.0f / den;

    // epilogue: normalize, +b2, ELU, dot with W3 columns
    float v0 = acc0 * inv + sb2[col];
    float v1 = acc1 * inv + sb2[col + 1];
    v0 = v0 > 0.0f ? v0 : expm1f(v0);
    v1 = v1 > 0.0f ? v1 : expm1f(v1);
    float a0 = v0 * sW3[col * 2]       + v1 * sW3[(col + 1) * 2];
    float a1 = v0 * sW3[col * 2 + 1]   + v1 * sW3[(col + 1) * 2 + 1];
    #pragma unroll
    for (int o = 16; o >= 1; o >>= 1) {
        a0 += __shfl_xor_sync(0xffffffffu, a0, o);
        a1 += __shfl_xor_sync(0xffffffffu, a1, o);
    }
    if (lane == 0) { sPart[wl][0] = a0; sPart[wl][1] = a1; }
    __syncthreads();
    if (tid < 2) {
        int n = blockIdx.x * 2 + tid;
        int b = tid * 4;
        g_hw3[(size_t)n * 2] =
            sPart[b][0] + sPart[b + 1][0] + sPart[b + 2][0] + sPart[b + 3][0];
        g_hw3[(size_t)n * 2 + 1] =
            sPart[b][1] + sPart[b + 1][1] + sPart[b + 2][1] + sPart[b + 3][1];
    }
}

// ---------------- GCN-2 gather ----------------------------------------------
__global__ void k_gcn2(const float* __restrict__ b3, float* __restrict__ out) {
    int warp = (blockIdx.x * blockDim.x + threadIdx.x) >> 5;
    int lane = threadIdx.x & 31;
    if (warp >= N_NODES) return;
    int r0 = g_rowptr[warp], r1 = g_rowptr[warp + 1];
    float acc0 = 0.0f, acc1 = 0.0f;
    for (int e = r0 + lane; e < r1; e += 32) {
        Edge ed = g_csr[e];
        float2 v = *(const float2*)&g_hw3[(size_t)ed.src * 2];
        acc0 += v.x * ed.norm; acc1 += v.y * ed.norm;
    }
    #pragma unroll
    for (int o = 16; o >= 1; o >>= 1) {
        acc0 += __shfl_xor_sync(0xffffffffu, acc0, o);
        acc1 += __shfl_xor_sync(0xffffffffu, acc1, o);
    }
    if (lane == 0) {
        out[(size_t)warp * 2]     = acc0 + __ldg(&b3[0]);
        out[(size_t)warp * 2 + 1] = acc1 + __ldg(&b3[1]);
    }
}

// ---------------- launch -------------------------------------------------------
extern "C" void kernel_launch(void* const* d_in, const int* in_sizes, int n_in,
                              void* d_out, int out_size) {
    const float* x    = (const float*)d_in[0];
    const int*   ei   = (const int*)d_in[1];
    const float* W1   = (const float*)d_in[2];
    const float* b1   = (const float*)d_in[3];
    const float* W2   = (const float*)d_in[4];
    const float* attS = (const float*)d_in[5];
    const float* attD = (const float*)d_in[6];
    const float* b2   = (const float*)d_in[7];
    const float* W3   = (const float*)d_in[8];
    const float* b3   = (const float*)d_in[9];
    float* out = (float*)d_out;

    const int T = 256;
    const int RB = (N_NODES + 63) / 64;
    k_init  <<<(N_NODES + T - 1) / T, T>>>();
    k_edges <<<(E2 + T - 1) / T, T>>>(ei);
    k_scan  <<<1, SCAN_T>>>();
    k_fill  <<<(E2 + T - 1) / T, T>>>(ei);
    k_gemm1 <<<RB, T>>>(x, W1);
    k_gcn1  <<<(N_NODES * 32 + T - 1) / T, T>>>(b1);
    k_gemm2 <<<dim3(RB, HEADS), T>>>(W2, attS, attD);
    k_maxred<<<(N_NODES + T - 1) / T, T>>>();
    k_gat   <<<N_NODES / 2, T>>>(b2, W3);
    k_gcn2  <<<(N_NODES * 32 + T - 1) / T, T>>>(b3, out);
}

// round 9
// speedup vs baseline: 1.1725x; 1.1725x over previous
#include <cuda_runtime.h>
#include <cuda_fp16.h>
#include <math.h>

#define N_NODES 100000
#define E_EDGES 1600000
#define E2      (E_EDGES + N_NODES)   // 1,700,000
#define IN_C    128
#define HID     64
#define HEADS   4
#define HH      (HEADS * HID)         // 256
#define OUT_C   2
#define NEG_SLOPE 0.2f
#define SCAN_T  1024

struct Edge { int src; float norm; };

// ---------------- scratch ----------------------------------------------------
__device__ __align__(16) int    g_degi[N_NODES];
__device__ __align__(16) int    g_cnt[N_NODES];
__device__ __align__(16) int    g_rowptr[N_NODES + 1];
__device__ __align__(16) float  g_dinv[N_NODES];
__device__ __align__(16) Edge   g_csr[E2];
__device__ __align__(16) __half g_xw1h[(size_t)N_NODES * HID];
__device__ __align__(16) float  g_h0 [(size_t)N_NODES * HID];
__device__ __align__(16) __half g_xw2h[(size_t)N_NODES * HH];    // 51MB, L2-resident
__device__ __align__(16) float  g_as [(size_t)N_NODES * HEADS];
__device__ __align__(16) float  g_ad [(size_t)N_NODES * HEADS];
__device__ __align__(16) float  g_mx[8];
__device__ __align__(16) float  g_hw3[(size_t)N_NODES * OUT_C];

__device__ __forceinline__ float lrelu(float x) { return x > 0.0f ? x : NEG_SLOPE * x; }

__device__ __forceinline__ void atomicMaxFloat(float* addr, float value) {
    if (value >= 0.0f) atomicMax((int*)addr, __float_as_int(value));
    else               atomicMin((unsigned int*)addr, __float_as_uint(value));
}

// ---------------- CSR build --------------------------------------------------
__global__ void k_init() {
    int i = blockIdx.x * blockDim.x + threadIdx.x;
    if (i < N_NODES) { g_degi[i] = 0; g_cnt[i] = 0; }
    if (i < 8) g_mx[i] = -3.402823466e38f;
}

__global__ void k_edges(const int* __restrict__ ei) {
    int e = blockIdx.x * blockDim.x + threadIdx.x;
    if (e >= E2) return;
    int d = (e < E_EDGES) ? ei[E_EDGES + e] : (e - E_EDGES);
    atomicAdd(&g_degi[d], 1);
}

__global__ void k_scan() {
    __shared__ int part[SCAN_T];
    const int CH = (N_NODES + SCAN_T - 1) / SCAN_T;
    int t = threadIdx.x;
    int base = t * CH;
    int hi = min(base + CH, N_NODES);
    int sum = 0;
    for (int i = base; i < hi; i++) sum += g_degi[i];
    part[t] = sum;
    __syncthreads();
    for (int off = 1; off < SCAN_T; off <<= 1) {
        int v = (t >= off) ? part[t - off] : 0;
        __syncthreads();
        part[t] += v;
        __syncthreads();
    }
    int run = (t == 0) ? 0 : part[t - 1];
    for (int i = base; i < hi; i++) {
        g_rowptr[i] = run;
        int dg = g_degi[i];
        g_dinv[i] = dg > 0 ? rsqrtf((float)dg) : 0.0f;
        run += dg;
    }
    if (t == SCAN_T - 1) g_rowptr[N_NODES] = run;
}

__global__ void k_fill(const int* __restrict__ ei) {
    int e = blockIdx.x * blockDim.x + threadIdx.x;
    if (e >= E2) return;
    int s, d;
    if (e < E_EDGES) { s = ei[e]; d = ei[E_EDGES + e]; }
    else             { s = e - E_EDGES; d = s; }
    int pos = g_rowptr[d] + atomicAdd(&g_cnt[d], 1);
    Edge ed; ed.src = s; ed.norm = g_dinv[s] * g_dinv[d];
    g_csr[pos] = ed;
}

// ---------------- GEMM 1: xw1h = fp16(x @ W1)   64x64 tile, 4x4/thread -----
__global__ void __launch_bounds__(256) k_gemm1(const float* __restrict__ x,
                                               const float* __restrict__ W1) {
    __shared__ __align__(16) float As[64][68];
    __shared__ __align__(16) float Bs[64][HID];
    int tid = threadIdx.x;
    int tx = tid & 15, ty = tid >> 4;
    int row0 = blockIdx.x * 64;
    float acc[4][4];
    #pragma unroll
    for (int i = 0; i < 4; i++)
        #pragma unroll
        for (int j = 0; j < 4; j++) acc[i][j] = 0.0f;

    for (int kc = 0; kc < IN_C; kc += 64) {
        __syncthreads();
        #pragma unroll
        for (int it = 0; it < 4; it++) {
            int idx = tid + it * 256;
            int r = idx >> 4, k4 = idx & 15;
            int row = row0 + r;
            float4 v = make_float4(0.f, 0.f, 0.f, 0.f);
            if (row < N_NODES)
                v = *(const float4*)&x[(size_t)row * IN_C + kc + k4 * 4];
            *(float4*)&As[r][k4 * 4] = v;
        }
        #pragma unroll
        for (int it = 0; it < 4; it++) {
            int idx = tid + it * 256;
            int k = idx >> 4, c4 = idx & 15;
            *(float4*)&Bs[k][c4 * 4] = *(const float4*)&W1[(size_t)(kc + k) * HID + c4 * 4];
        }
        __syncthreads();
        #pragma unroll 16
        for (int k = 0; k < 64; k++) {
            float a0 = As[ty * 4 + 0][k], a1 = As[ty * 4 + 1][k];
            float a2 = As[ty * 4 + 2][k], a3 = As[ty * 4 + 3][k];
            float4 b = *(const float4*)&Bs[k][tx * 4];
            acc[0][0] += a0 * b.x; acc[0][1] += a0 * b.y; acc[0][2] += a0 * b.z; acc[0][3] += a0 * b.w;
            acc[1][0] += a1 * b.x; acc[1][1] += a1 * b.y; acc[1][2] += a1 * b.z; acc[1][3] += a1 * b.w;
            acc[2][0] += a2 * b.x; acc[2][1] += a2 * b.y; acc[2][2] += a2 * b.z; acc[2][3] += a2 * b.w;
            acc[3][0] += a3 * b.x; acc[3][1] += a3 * b.y; acc[3][2] += a3 * b.z; acc[3][3] += a3 * b.w;
        }
    }
    #pragma unroll
    for (int i = 0; i < 4; i++) {
        int row = row0 + ty * 4 + i;
        if (row < N_NODES) {
            __half2 p0 = __floats2half2_rn(acc[i][0], acc[i][1]);
            __half2 p1 = __floats2half2_rn(acc[i][2], acc[i][3]);
            uint2 u; u.x = *(unsigned*)&p0; u.y = *(unsigned*)&p1;
            *(uint2*)&g_xw1h[(size_t)row * HID + tx * 4] = u;
        }
    }
}

// ---------------- GCN-1 gather (fp16, 4-unroll, csr pipelined) -------------
__global__ void k_gcn1(const float* __restrict__ b1) {
    int warp = (blockIdx.x * blockDim.x + threadIdx.x) >> 5;
    int lane = threadIdx.x & 31;
    if (warp >= N_NODES) return;
    int r0 = g_rowptr[warp], r1 = g_rowptr[warp + 1];
    float acc0 = 0.0f, acc1 = 0.0f;
    int off = lane * 2;

    Edge p0, p1, p2, p3;
    int e = r0;
    if (e + 4 <= r1) { p0 = g_csr[e]; p1 = g_csr[e + 1]; p2 = g_csr[e + 2]; p3 = g_csr[e + 3]; }
    for (; e + 4 <= r1; e += 4) {
        Edge e0 = p0, e1 = p1, e2 = p2, e3 = p3;
        if (e + 8 <= r1) { p0 = g_csr[e + 4]; p1 = g_csr[e + 5]; p2 = g_csr[e + 6]; p3 = g_csr[e + 7]; }
        __half2 h0 = *(const __half2*)&g_xw1h[(size_t)e0.src * HID + off];
        __half2 h1 = *(const __half2*)&g_xw1h[(size_t)e1.src * HID + off];
        __half2 h2 = *(const __half2*)&g_xw1h[(size_t)e2.src * HID + off];
        __half2 h3 = *(const __half2*)&g_xw1h[(size_t)e3.src * HID + off];
        float2 v0 = __half22float2(h0), v1 = __half22float2(h1);
        float2 v2 = __half22float2(h2), v3 = __half22float2(h3);
        acc0 += v0.x * e0.norm + v1.x * e1.norm + v2.x * e2.norm + v3.x * e3.norm;
        acc1 += v0.y * e0.norm + v1.y * e1.norm + v2.y * e2.norm + v3.y * e3.norm;
    }
    for (; e < r1; e++) {
        Edge ed = g_csr[e];
        float2 v = __half22float2(*(const __half2*)&g_xw1h[(size_t)ed.src * HID + off]);
        acc0 += v.x * ed.norm; acc1 += v.y * ed.norm;
    }
    float2 o;
    o.x = fmaxf(acc0 + __ldg(&b1[off]),     0.0f);
    o.y = fmaxf(acc1 + __ldg(&b1[off + 1]), 0.0f);
    *(float2*)&g_h0[(size_t)warp * HID + off] = o;
}

// ---------------- GEMM 2: xw2h = fp16(h0 @ W2), + attention dots -----------
__global__ void __launch_bounds__(256) k_gemm2(const float* __restrict__ W2,
                                               const float* __restrict__ attS,
                                               const float* __restrict__ attD) {
    __shared__ __align__(16) float As[64][68];
    __shared__ __align__(16) float Bs[64][64];
    __shared__ float sa[64], sd[64];
    int tid = threadIdx.x;
    int tx = tid & 15, ty = tid >> 4;
    int head = blockIdx.y;
    int row0 = blockIdx.x * 64;

    #pragma unroll
    for (int it = 0; it < 4; it++) {
        int idx = tid + it * 256;
        int r = idx >> 4, k4 = idx & 15;
        int row = row0 + r;
        float4 v = make_float4(0.f, 0.f, 0.f, 0.f);
        if (row < N_NODES)
            v = *(const float4*)&g_h0[(size_t)row * HID + k4 * 4];
        *(float4*)&As[r][k4 * 4] = v;
    }
    #pragma unroll
    for (int it = 0; it < 4; it++) {
        int idx = tid + it * 256;
        int k = idx >> 4, c4 = idx & 15;
        *(float4*)&Bs[k][c4 * 4] =
            *(const float4*)&W2[(size_t)k * HH + head * 64 + c4 * 4];
    }
    if (tid < 64) { sa[tid] = attS[head * 64 + tid]; sd[tid] = attD[head * 64 + tid]; }
    __syncthreads();

    float acc[4][4];
    #pragma unroll
    for (int i = 0; i < 4; i++)
        #pragma unroll
        for (int j = 0; j < 4; j++) acc[i][j] = 0.0f;

    #pragma unroll 16
    for (int k = 0; k < 64; k++) {
        float a0 = As[ty * 4 + 0][k], a1 = As[ty * 4 + 1][k];
        float a2 = As[ty * 4 + 2][k], a3 = As[ty * 4 + 3][k];
        float4 b = *(const float4*)&Bs[k][tx * 4];
        acc[0][0] += a0 * b.x; acc[0][1] += a0 * b.y; acc[0][2] += a0 * b.z; acc[0][3] += a0 * b.w;
        acc[1][0] += a1 * b.x; acc[1][1] += a1 * b.y; acc[1][2] += a1 * b.z; acc[1][3] += a1 * b.w;
        acc[2][0] += a2 * b.x; acc[2][1] += a2 * b.y; acc[2][2] += a2 * b.z; acc[2][3] += a2 * b.w;
        acc[3][0] += a3 * b.x; acc[3][1] += a3 * b.y; acc[3][2] += a3 * b.z; acc[3][3] += a3 * b.w;
    }

    #pragma unroll
    for (int i = 0; i < 4; i++) {
        int row = row0 + ty * 4 + i;
        if (row < N_NODES) {
            __half2 p0 = __floats2half2_rn(acc[i][0], acc[i][1]);
            __half2 p1 = __floats2half2_rn(acc[i][2], acc[i][3]);
            uint2 u; u.x = *(unsigned*)&p0; u.y = *(unsigned*)&p1;
            *(uint2*)&g_xw2h[(size_t)row * HH + head * 64 + tx * 4] = u;
        }
    }

    float ps[4], pd[4];
    #pragma unroll
    for (int i = 0; i < 4; i++) {
        float s = 0.f, d = 0.f;
        #pragma unroll
        for (int j = 0; j < 4; j++) {
            s += acc[i][j] * sa[tx * 4 + j];
            d += acc[i][j] * sd[tx * 4 + j];
        }
        ps[i] = s; pd[i] = d;
    }
    #pragma unroll
    for (int off = 8; off >= 1; off >>= 1) {
        #pragma unroll
        for (int i = 0; i < 4; i++) {
            ps[i] += __shfl_xor_sync(0xffffffffu, ps[i], off);
            pd[i] += __shfl_xor_sync(0xffffffffu, pd[i], off);
        }
    }
    if (tx == 0) {
        #pragma unroll
        for (int i = 0; i < 4; i++) {
            int row = row0 + ty * 4 + i;
            if (row < N_NODES) {
                g_as[(size_t)row * HEADS + head] = ps[i];
                g_ad[(size_t)row * HEADS + head] = pd[i];
            }
        }
    }
}

// ---------------- global per-head max of a_s / a_d -------------------------
__global__ void k_maxred() {
    int i = blockIdx.x * blockDim.x + threadIdx.x;
    int lane = threadIdx.x & 31;
    float4 a = make_float4(-3.4e38f, -3.4e38f, -3.4e38f, -3.4e38f);
    float4 d = a;
    if (i < N_NODES) {
        a = *(const float4*)&g_as[(size_t)i * HEADS];
        d = *(const float4*)&g_ad[(size_t)i * HEADS];
    }
    #pragma unroll
    for (int o = 16; o >= 1; o >>= 1) {
        a.x = fmaxf(a.x, __shfl_xor_sync(0xffffffffu, a.x, o));
        a.y = fmaxf(a.y, __shfl_xor_sync(0xffffffffu, a.y, o));
        a.z = fmaxf(a.z, __shfl_xor_sync(0xffffffffu, a.z, o));
        a.w = fmaxf(a.w, __shfl_xor_sync(0xffffffffu, a.w, o));
        d.x = fmaxf(d.x, __shfl_xor_sync(0xffffffffu, d.x, o));
        d.y = fmaxf(d.y, __shfl_xor_sync(0xffffffffu, d.y, o));
        d.z = fmaxf(d.z, __shfl_xor_sync(0xffffffffu, d.z, o));
        d.w = fmaxf(d.w, __shfl_xor_sync(0xffffffffu, d.w, o));
    }
    if (lane == 0) {
        atomicMaxFloat(&g_mx[0], a.x); atomicMaxFloat(&g_mx[1], a.y);
        atomicMaxFloat(&g_mx[2], a.z); atomicMaxFloat(&g_mx[3], a.w);
        atomicMaxFloat(&g_mx[4], d.x); atomicMaxFloat(&g_mx[5], d.y);
        atomicMaxFloat(&g_mx[6], d.z); atomicMaxFloat(&g_mx[7], d.w);
    }
}

// ---------------- fused GAT: 2 warps per node, csr-pipelined ---------------
// block = 256 threads = 8 warps = 4 nodes; grid = 25000 exact.
__global__ void __launch_bounds__(256) k_gat(const float* __restrict__ b2,
                                             const float* __restrict__ W3) {
    __shared__ float sW3[HH * 2];
    __shared__ float sb2[HH];
    __shared__ float sC[HEADS];
    __shared__ float sPart[8][2];
    int tid = threadIdx.x;
    sW3[tid * 2]     = W3[tid * 2];
    sW3[tid * 2 + 1] = W3[tid * 2 + 1];
    sb2[tid]         = b2[tid];
    if (tid < HEADS) sC[tid] = lrelu(g_mx[tid] + g_mx[tid + 4]);
    __syncthreads();

    int wlocal = tid >> 5;                       // 0..7
    int node   = blockIdx.x * 4 + (wlocal >> 1);
    int hpart  = wlocal & 1;                     // which 128-channel half
    int lane   = tid & 31;
    int r0 = g_rowptr[node], r1 = g_rowptr[node + 1];

    int col  = hpart * 128 + lane * 4;           // 4 fp16 channels per lane
    int head = col >> 6;
    float adh = g_ad[(size_t)node * HEADS + head];
    float Ch  = sC[head];

    float acc[4];
    #pragma unroll
    for (int j = 0; j < 4; j++) acc[j] = 0.0f;
    float den = 0.0f;

    int p0 = 0, p1 = 0, p2 = 0, p3 = 0;
    int e = r0;
    if (e + 4 <= r1) {
        p0 = g_csr[e].src;     p1 = g_csr[e + 1].src;
        p2 = g_csr[e + 2].src; p3 = g_csr[e + 3].src;
    }
    for (; e + 4 <= r1; e += 4) {
        int s0 = p0, s1 = p1, s2 = p2, s3 = p3;
        if (e + 8 <= r1) {
            p0 = g_csr[e + 4].src; p1 = g_csr[e + 5].src;
            p2 = g_csr[e + 6].src; p3 = g_csr[e + 7].src;
        }
        float as0 = g_as[(size_t)s0 * HEADS + head];
        float as1 = g_as[(size_t)s1 * HEADS + head];
        float as2 = g_as[(size_t)s2 * HEADS + head];
        float as3 = g_as[(size_t)s3 * HEADS + head];
        uint2 u0 = *(const uint2*)&g_xw2h[(size_t)s0 * HH + col];
        uint2 u1 = *(const uint2*)&g_xw2h[(size_t)s1 * HH + col];
        uint2 u2 = *(const uint2*)&g_xw2h[(size_t)s2 * HH + col];
        uint2 u3 = *(const uint2*)&g_xw2h[(size_t)s3 * HH + col];
        float w0 = __expf(lrelu(as0 + adh) - Ch);
        float w1 = __expf(lrelu(as1 + adh) - Ch);
        float w2 = __expf(lrelu(as2 + adh) - Ch);
        float w3 = __expf(lrelu(as3 + adh) - Ch);
        den += (w0 + w1) + (w2 + w3);
        float2 f;
        f = __half22float2(*(__half2*)&u0.x); acc[0] += f.x * w0; acc[1] += f.y * w0;
        f = __half22float2(*(__half2*)&u0.y); acc[2] += f.x * w0; acc[3] += f.y * w0;
        f = __half22float2(*(__half2*)&u1.x); acc[0] += f.x * w1; acc[1] += f.y * w1;
        f = __half22float2(*(__half2*)&u1.y); acc[2] += f.x * w1; acc[3] += f.y * w1;
        f = __half22float2(*(__half2*)&u2.x); acc[0] += f.x * w2; acc[1] += f.y * w2;
        f = __half22float2(*(__half2*)&u2.y); acc[2] += f.x * w2; acc[3] += f.y * w2;
        f = __half22float2(*(__half2*)&u3.x); acc[0] += f.x * w3; acc[1] += f.y * w3;
        f = __half22float2(*(__half2*)&u3.y); acc[2] += f.x * w3; acc[3] += f.y * w3;
    }
    for (; e < r1; e++) {
        int s = g_csr[e].src;
        float ash = g_as[(size_t)s * HEADS + head];
        float w = __expf(lrelu(ash + adh) - Ch);
        den += w;
        uint2 u = *(const uint2*)&g_xw2h[(size_t)s * HH + col];
        float2 f;
        f = __half22float2(*(__half2*)&u.x); acc[0] += f.x * w; acc[1] += f.y * w;
        f = __half22float2(*(__half2*)&u.y); acc[2] += f.x * w; acc[3] += f.y * w;
    }
    float inv = 1.0f / den;

    float a0 = 0.0f, a1 = 0.0f;
    #pragma unroll
    for (int j = 0; j < 4; j++) {
        int c = col + j;
        float v = acc[j] * inv + sb2[c];
        v = v > 0.0f ? v : expm1f(v);
        a0 += v * sW3[c * 2];
        a1 += v * sW3[c * 2 + 1];
    }
    #pragma unroll
    for (int o = 16; o >= 1; o >>= 1) {
        a0 += __shfl_xor_sync(0xffffffffu, a0, o);
        a1 += __shfl_xor_sync(0xffffffffu, a1, o);
    }
    if (lane == 0) { sPart[wlocal][0] = a0; sPart[wlocal][1] = a1; }
    __syncthreads();
    if (tid < 4) {
        int n = blockIdx.x * 4 + tid;
        g_hw3[(size_t)n * 2]     = sPart[tid * 2][0] + sPart[tid * 2 + 1][0];
        g_hw3[(size_t)n * 2 + 1] = sPart[tid * 2][1] + sPart[tid * 2 + 1][1];
    }
}

// ---------------- GCN-2 gather ----------------------------------------------
__global__ void k_gcn2(const float* __restrict__ b3, float* __restrict__ out) {
    int warp = (blockIdx.x * blockDim.x + threadIdx.x) >> 5;
    int lane = threadIdx.x & 31;
    if (warp >= N_NODES) return;
    int r0 = g_rowptr[warp], r1 = g_rowptr[warp + 1];
    float acc0 = 0.0f, acc1 = 0.0f;
    for (int e = r0 + lane; e < r1; e += 32) {
        Edge ed = g_csr[e];
        float2 v = *(const float2*)&g_hw3[(size_t)ed.src * 2];
        acc0 += v.x * ed.norm; acc1 += v.y * ed.norm;
    }
    #pragma unroll
    for (int o = 16; o >= 1; o >>= 1) {
        acc0 += __shfl_xor_sync(0xffffffffu, acc0, o);
        acc1 += __shfl_xor_sync(0xffffffffu, acc1, o);
    }
    if (lane == 0) {
        out[(size_t)warp * 2]     = acc0 + __ldg(&b3[0]);
        out[(size_t)warp * 2 + 1] = acc1 + __ldg(&b3[1]);
    }
}

// ---------------- launch -------------------------------------------------------
extern "C" void kernel_launch(void* const* d_in, const int* in_sizes, int n_in,
                              void* d_out, int out_size) {
    const float* x    = (const float*)d_in[0];
    const int*   ei   = (const int*)d_in[1];
    const float* W1   = (const float*)d_in[2];
    const float* b1   = (const float*)d_in[3];
    const float* W2   = (const float*)d_in[4];
    const float* attS = (const float*)d_in[5];
    const float* attD = (const float*)d_in[6];
    const float* b2   = (const float*)d_in[7];
    const float* W3   = (const float*)d_in[8];
    const float* b3   = (const float*)d_in[9];
    float* out = (float*)d_out;

    const int T = 256;
    const int RB = (N_NODES + 63) / 64;
    k_init  <<<(N_NODES + T - 1) / T, T>>>();
    k_edges <<<(E2 + T - 1) / T, T>>>(ei);
    k_scan  <<<1, SCAN_T>>>();
    k_fill  <<<(E2 + T - 1) / T, T>>>(ei);
    k_gemm1 <<<RB, T>>>(x, W1);
    k_gcn1  <<<(N_NODES * 32 + T - 1) / T, T>>>(b1);
    k_gemm2 <<<dim3(RB, HEADS), T>>>(W2, attS, attD);
    k_maxred<<<(N_NODES + T - 1) / T, T>>>();
    k_gat   <<<N_NODES / 4, T>>>(b2, W3);
    k_gcn2  <<<(N_NODES * 32 + T - 1) / T, T>>>(b3, out);
}

// round 10
// speedup vs baseline: 1.1979x; 1.0217x over previous
#include <cuda_runtime.h>
#include <cuda_fp16.h>
#include <math.h>

#define N_NODES 100000
#define E_EDGES 1600000
#define E2      (E_EDGES + N_NODES)   // 1,700,000
#define IN_C    128
#define HID     64
#define HEADS   4
#define HH      (HEADS * HID)         // 256
#define OUT_C   2
#define NEG_SLOPE 0.2f
#define SCAN_T  1024

struct Edge { int src; float norm; };

// ---------------- scratch ----------------------------------------------------
__device__ __align__(16) int    g_degi[N_NODES];
__device__ __align__(16) int    g_cnt[N_NODES];
__device__ __align__(16) int    g_rowptr[N_NODES + 1];
__device__ __align__(16) float  g_dinv[N_NODES];
__device__ __align__(16) Edge   g_csr[E2];
__device__ __align__(16) int    g_dstc[E2];
__device__ __align__(16) float4 g_w4[E2];                        // per-edge softmax weights (4 heads)
__device__ __align__(16) __half g_xw1h[(size_t)N_NODES * HID];
__device__ __align__(16) float  g_h0 [(size_t)N_NODES * HID];
__device__ __align__(16) __half g_xw2h[(size_t)N_NODES * HH];    // 51MB
__device__ __align__(16) float  g_as [(size_t)N_NODES * HEADS];
__device__ __align__(16) float  g_ad [(size_t)N_NODES * HEADS];
__device__ __align__(16) float  g_mx[8];
__device__ __align__(16) float  g_hw3[(size_t)N_NODES * OUT_C];

__device__ __forceinline__ float lrelu(float x) { return x > 0.0f ? x : NEG_SLOPE * x; }

__device__ __forceinline__ void atomicMaxFloat(float* addr, float value) {
    if (value >= 0.0f) atomicMax((int*)addr, __float_as_int(value));
    else               atomicMin((unsigned int*)addr, __float_as_uint(value));
}

// ---------------- CSR build --------------------------------------------------
__global__ void k_init() {
    int i = blockIdx.x * blockDim.x + threadIdx.x;
    if (i < N_NODES) { g_degi[i] = 0; g_cnt[i] = 0; }
    if (i < 8) g_mx[i] = -3.402823466e38f;
}

__global__ void k_edges(const int* __restrict__ ei) {
    int e = blockIdx.x * blockDim.x + threadIdx.x;
    if (e >= E2) return;
    int d = (e < E_EDGES) ? ei[E_EDGES + e] : (e - E_EDGES);
    atomicAdd(&g_degi[d], 1);
}

__global__ void k_scan() {
    __shared__ int part[SCAN_T];
    const int CH = (N_NODES + SCAN_T - 1) / SCAN_T;
    int t = threadIdx.x;
    int base = t * CH;
    int hi = min(base + CH, N_NODES);
    int sum = 0;
    for (int i = base; i < hi; i++) sum += g_degi[i];
    part[t] = sum;
    __syncthreads();
    for (int off = 1; off < SCAN_T; off <<= 1) {
        int v = (t >= off) ? part[t - off] : 0;
        __syncthreads();
        part[t] += v;
        __syncthreads();
    }
    int run = (t == 0) ? 0 : part[t - 1];
    for (int i = base; i < hi; i++) {
        g_rowptr[i] = run;
        int dg = g_degi[i];
        g_dinv[i] = dg > 0 ? rsqrtf((float)dg) : 0.0f;
        run += dg;
    }
    if (t == SCAN_T - 1) g_rowptr[N_NODES] = run;
}

__global__ void k_fill(const int* __restrict__ ei) {
    int e = blockIdx.x * blockDim.x + threadIdx.x;
    if (e >= E2) return;
    int s, d;
    if (e < E_EDGES) { s = ei[e]; d = ei[E_EDGES + e]; }
    else             { s = e - E_EDGES; d = s; }
    int pos = g_rowptr[d] + atomicAdd(&g_cnt[d], 1);
    Edge ed; ed.src = s; ed.norm = g_dinv[s] * g_dinv[d];
    g_csr[pos]  = ed;
    g_dstc[pos] = d;
}

// ---------------- GEMM 1: xw1h = fp16(x @ W1)   64x64 tile, 4x4/thread -----
__global__ void __launch_bounds__(256) k_gemm1(const float* __restrict__ x,
                                               const float* __restrict__ W1) {
    __shared__ __align__(16) float As[64][68];
    __shared__ __align__(16) float Bs[64][HID];
    int tid = threadIdx.x;
    int tx = tid & 15, ty = tid >> 4;
    int row0 = blockIdx.x * 64;
    float acc[4][4];
    #pragma unroll
    for (int i = 0; i < 4; i++)
        #pragma unroll
        for (int j = 0; j < 4; j++) acc[i][j] = 0.0f;

    for (int kc = 0; kc < IN_C; kc += 64) {
        __syncthreads();
        #pragma unroll
        for (int it = 0; it < 4; it++) {
            int idx = tid + it * 256;
            int r = idx >> 4, k4 = idx & 15;
            int row = row0 + r;
            float4 v = make_float4(0.f, 0.f, 0.f, 0.f);
            if (row < N_NODES)
                v = *(const float4*)&x[(size_t)row * IN_C + kc + k4 * 4];
            *(float4*)&As[r][k4 * 4] = v;
        }
        #pragma unroll
        for (int it = 0; it < 4; it++) {
            int idx = tid + it * 256;
            int k = idx >> 4, c4 = idx & 15;
            *(float4*)&Bs[k][c4 * 4] = *(const float4*)&W1[(size_t)(kc + k) * HID + c4 * 4];
        }
        __syncthreads();
        #pragma unroll 16
        for (int k = 0; k < 64; k++) {
            float a0 = As[ty * 4 + 0][k], a1 = As[ty * 4 + 1][k];
            float a2 = As[ty * 4 + 2][k], a3 = As[ty * 4 + 3][k];
            float4 b = *(const float4*)&Bs[k][tx * 4];
            acc[0][0] += a0 * b.x; acc[0][1] += a0 * b.y; acc[0][2] += a0 * b.z; acc[0][3] += a0 * b.w;
            acc[1][0] += a1 * b.x; acc[1][1] += a1 * b.y; acc[1][2] += a1 * b.z; acc[1][3] += a1 * b.w;
            acc[2][0] += a2 * b.x; acc[2][1] += a2 * b.y; acc[2][2] += a2 * b.z; acc[2][3] += a2 * b.w;
            acc[3][0] += a3 * b.x; acc[3][1] += a3 * b.y; acc[3][2] += a3 * b.z; acc[3][3] += a3 * b.w;
        }
    }
    #pragma unroll
    for (int i = 0; i < 4; i++) {
        int row = row0 + ty * 4 + i;
        if (row < N_NODES) {
            __half2 p0 = __floats2half2_rn(acc[i][0], acc[i][1]);
            __half2 p1 = __floats2half2_rn(acc[i][2], acc[i][3]);
            uint2 u; u.x = *(unsigned*)&p0; u.y = *(unsigned*)&p1;
            *(uint2*)&g_xw1h[(size_t)row * HID + tx * 4] = u;
        }
    }
}

// ---------------- GCN-1 gather (fp16, 4-unroll) ----------------------------
__global__ void k_gcn1(const float* __restrict__ b1) {
    int warp = (blockIdx.x * blockDim.x + threadIdx.x) >> 5;
    int lane = threadIdx.x & 31;
    if (warp >= N_NODES) return;
    int r0 = g_rowptr[warp], r1 = g_rowptr[warp + 1];
    float acc0 = 0.0f, acc1 = 0.0f;
    int off = lane * 2;
    int e = r0;
    for (; e + 4 <= r1; e += 4) {
        Edge e0 = g_csr[e], e1 = g_csr[e + 1], e2 = g_csr[e + 2], e3 = g_csr[e + 3];
        __half2 h0 = *(const __half2*)&g_xw1h[(size_t)e0.src * HID + off];
        __half2 h1 = *(const __half2*)&g_xw1h[(size_t)e1.src * HID + off];
        __half2 h2 = *(const __half2*)&g_xw1h[(size_t)e2.src * HID + off];
        __half2 h3 = *(const __half2*)&g_xw1h[(size_t)e3.src * HID + off];
        float2 v0 = __half22float2(h0), v1 = __half22float2(h1);
        float2 v2 = __half22float2(h2), v3 = __half22float2(h3);
        acc0 += v0.x * e0.norm + v1.x * e1.norm + v2.x * e2.norm + v3.x * e3.norm;
        acc1 += v0.y * e0.norm + v1.y * e1.norm + v2.y * e2.norm + v3.y * e3.norm;
    }
    for (; e < r1; e++) {
        Edge ed = g_csr[e];
        float2 v = __half22float2(*(const __half2*)&g_xw1h[(size_t)ed.src * HID + off]);
        acc0 += v.x * ed.norm; acc1 += v.y * ed.norm;
    }
    float2 o;
    o.x = fmaxf(acc0 + __ldg(&b1[off]),     0.0f);
    o.y = fmaxf(acc1 + __ldg(&b1[off + 1]), 0.0f);
    *(float2*)&g_h0[(size_t)warp * HID + off] = o;
}

// ---------------- GEMM 2: xw2h = fp16(h0 @ W2), + attention dots -----------
__global__ void __launch_bounds__(256) k_gemm2(const float* __restrict__ W2,
                                               const float* __restrict__ attS,
                                               const float* __restrict__ attD) {
    __shared__ __align__(16) float As[64][68];
    __shared__ __align__(16) float Bs[64][64];
    __shared__ float sa[64], sd[64];
    int tid = threadIdx.x;
    int tx = tid & 15, ty = tid >> 4;
    int head = blockIdx.y;
    int row0 = blockIdx.x * 64;

    #pragma unroll
    for (int it = 0; it < 4; it++) {
        int idx = tid + it * 256;
        int r = idx >> 4, k4 = idx & 15;
        int row = row0 + r;
        float4 v = make_float4(0.f, 0.f, 0.f, 0.f);
        if (row < N_NODES)
            v = *(const float4*)&g_h0[(size_t)row * HID + k4 * 4];
        *(float4*)&As[r][k4 * 4] = v;
    }
    #pragma unroll
    for (int it = 0; it < 4; it++) {
        int idx = tid + it * 256;
        int k = idx >> 4, c4 = idx & 15;
        *(float4*)&Bs[k][c4 * 4] =
            *(const float4*)&W2[(size_t)k * HH + head * 64 + c4 * 4];
    }
    if (tid < 64) { sa[tid] = attS[head * 64 + tid]; sd[tid] = attD[head * 64 + tid]; }
    __syncthreads();

    float acc[4][4];
    #pragma unroll
    for (int i = 0; i < 4; i++)
        #pragma unroll
        for (int j = 0; j < 4; j++) acc[i][j] = 0.0f;

    #pragma unroll 16
    for (int k = 0; k < 64; k++) {
        float a0 = As[ty * 4 + 0][k], a1 = As[ty * 4 + 1][k];
        float a2 = As[ty * 4 + 2][k], a3 = As[ty * 4 + 3][k];
        float4 b = *(const float4*)&Bs[k][tx * 4];
        acc[0][0] += a0 * b.x; acc[0][1] += a0 * b.y; acc[0][2] += a0 * b.z; acc[0][3] += a0 * b.w;
        acc[1][0] += a1 * b.x; acc[1][1] += a1 * b.y; acc[1][2] += a1 * b.z; acc[1][3] += a1 * b.w;
        acc[2][0] += a2 * b.x; acc[2][1] += a2 * b.y; acc[2][2] += a2 * b.z; acc[2][3] += a2 * b.w;
        acc[3][0] += a3 * b.x; acc[3][1] += a3 * b.y; acc[3][2] += a3 * b.z; acc[3][3] += a3 * b.w;
    }

    #pragma unroll
    for (int i = 0; i < 4; i++) {
        int row = row0 + ty * 4 + i;
        if (row < N_NODES) {
            __half2 p0 = __floats2half2_rn(acc[i][0], acc[i][1]);
            __half2 p1 = __floats2half2_rn(acc[i][2], acc[i][3]);
            uint2 u; u.x = *(unsigned*)&p0; u.y = *(unsigned*)&p1;
            *(uint2*)&g_xw2h[(size_t)row * HH + head * 64 + tx * 4] = u;
        }
    }

    float ps[4], pd[4];
    #pragma unroll
    for (int i = 0; i < 4; i++) {
        float s = 0.f, d = 0.f;
        #pragma unroll
        for (int j = 0; j < 4; j++) {
            s += acc[i][j] * sa[tx * 4 + j];
            d += acc[i][j] * sd[tx * 4 + j];
        }
        ps[i] = s; pd[i] = d;
    }
    #pragma unroll
    for (int off = 8; off >= 1; off >>= 1) {
        #pragma unroll
        for (int i = 0; i < 4; i++) {
            ps[i] += __shfl_xor_sync(0xffffffffu, ps[i], off);
            pd[i] += __shfl_xor_sync(0xffffffffu, pd[i], off);
        }
    }
    if (tx == 0) {
        #pragma unroll
        for (int i = 0; i < 4; i++) {
            int row = row0 + ty * 4 + i;
            if (row < N_NODES) {
                g_as[(size_t)row * HEADS + head] = ps[i];
                g_ad[(size_t)row * HEADS + head] = pd[i];
            }
        }
    }
}

// ---------------- global per-head max of a_s / a_d -------------------------
__global__ void k_maxred() {
    int i = blockIdx.x * blockDim.x + threadIdx.x;
    int lane = threadIdx.x & 31;
    float4 a = make_float4(-3.4e38f, -3.4e38f, -3.4e38f, -3.4e38f);
    float4 d = a;
    if (i < N_NODES) {
        a = *(const float4*)&g_as[(size_t)i * HEADS];
        d = *(const float4*)&g_ad[(size_t)i * HEADS];
    }
    #pragma unroll
    for (int o = 16; o >= 1; o >>= 1) {
        a.x = fmaxf(a.x, __shfl_xor_sync(0xffffffffu, a.x, o));
        a.y = fmaxf(a.y, __shfl_xor_sync(0xffffffffu, a.y, o));
        a.z = fmaxf(a.z, __shfl_xor_sync(0xffffffffu, a.z, o));
        a.w = fmaxf(a.w, __shfl_xor_sync(0xffffffffu, a.w, o));
        d.x = fmaxf(d.x, __shfl_xor_sync(0xffffffffu, d.x, o));
        d.y = fmaxf(d.y, __shfl_xor_sync(0xffffffffu, d.y, o));
        d.z = fmaxf(d.z, __shfl_xor_sync(0xffffffffu, d.z, o));
        d.w = fmaxf(d.w, __shfl_xor_sync(0xffffffffu, d.w, o));
    }
    if (lane == 0) {
        atomicMaxFloat(&g_mx[0], a.x); atomicMaxFloat(&g_mx[1], a.y);
        atomicMaxFloat(&g_mx[2], a.z); atomicMaxFloat(&g_mx[3], a.w);
        atomicMaxFloat(&g_mx[4], d.x); atomicMaxFloat(&g_mx[5], d.y);
        atomicMaxFloat(&g_mx[6], d.z); atomicMaxFloat(&g_mx[7], d.w);
    }
}

// ---------------- edge-parallel softmax weights -----------------------------
// w[e][h] = exp(lrelu(a_s[src][h] + a_d[dst][h]) - C_h). Coalesced csr/dst
// reads; a_s gathered ONCE per edge; a_d reads are run-length (dst-sorted).
__global__ void k_weight() {
    int e = blockIdx.x * blockDim.x + threadIdx.x;
    if (e >= E2) return;
    float C0 = lrelu(g_mx[0] + g_mx[4]);
    float C1 = lrelu(g_mx[1] + g_mx[5]);
    float C2 = lrelu(g_mx[2] + g_mx[6]);
    float C3 = lrelu(g_mx[3] + g_mx[7]);
    int s = g_csr[e].src;
    int d = g_dstc[e];
    float4 a = *(const float4*)&g_as[(size_t)s * HEADS];
    float4 b = *(const float4*)&g_ad[(size_t)d * HEADS];
    float4 w;
    w.x = __expf(lrelu(a.x + b.x) - C0);
    w.y = __expf(lrelu(a.y + b.y) - C1);
    w.z = __expf(lrelu(a.z + b.z) - C2);
    w.w = __expf(lrelu(a.w + b.w) - C3);
    g_w4[e] = w;
}

// ---------------- fused GAT: 2 warps per node, precomputed weights ---------
// block = 256 = 8 warps = 4 nodes; grid = 25000 exact.
__global__ void __launch_bounds__(256) k_gat(const float* __restrict__ b2,
                                             const float* __restrict__ W3) {
    __shared__ float sW3[HH * 2];
    __shared__ float sb2[HH];
    __shared__ float sPart[8][2];
    int tid = threadIdx.x;
    sW3[tid * 2]     = W3[tid * 2];
    sW3[tid * 2 + 1] = W3[tid * 2 + 1];
    sb2[tid]         = b2[tid];
    __syncthreads();

    int wlocal = tid >> 5;                       // 0..7
    int node   = blockIdx.x * 4 + (wlocal >> 1);
    int hpart  = wlocal & 1;                     // 128-channel half
    int lane   = tid & 31;
    int r0 = g_rowptr[node], r1 = g_rowptr[node + 1];

    int col = hpart * 128 + lane * 4;            // 4 fp16 channels per lane
    bool hiHead = (lane & 16) != 0;              // lanes 16-31 use second head of the pair

    float acc[4];
    #pragma unroll
    for (int j = 0; j < 4; j++) acc[j] = 0.0f;
    float den = 0.0f;

    const float* wbase = (const float*)g_w4 + hpart * 2;   // head pair offset
    int e = r0;
    for (; e + 4 <= r1; e += 4) {
        int s0 = g_csr[e].src,     s1 = g_csr[e + 1].src;
        int s2 = g_csr[e + 2].src, s3 = g_csr[e + 3].src;
        float2 wp0 = *(const float2*)&wbase[(size_t)(e)     * 4];
        float2 wp1 = *(const float2*)&wbase[(size_t)(e + 1) * 4];
        float2 wp2 = *(const float2*)&wbase[(size_t)(e + 2) * 4];
        float2 wp3 = *(const float2*)&wbase[(size_t)(e + 3) * 4];
        uint2 u0 = *(const uint2*)&g_xw2h[(size_t)s0 * HH + col];
        uint2 u1 = *(const uint2*)&g_xw2h[(size_t)s1 * HH + col];
        uint2 u2 = *(const uint2*)&g_xw2h[(size_t)s2 * HH + col];
        uint2 u3 = *(const uint2*)&g_xw2h[(size_t)s3 * HH + col];
        float w0 = hiHead ? wp0.y : wp0.x;
        float w1 = hiHead ? wp1.y : wp1.x;
        float w2 = hiHead ? wp2.y : wp2.x;
        float w3 = hiHead ? wp3.y : wp3.x;
        den += (w0 + w1) + (w2 + w3);
        float2 f;
        f = __half22float2(*(__half2*)&u0.x); acc[0] += f.x * w0; acc[1] += f.y * w0;
        f = __half22float2(*(__half2*)&u0.y); acc[2] += f.x * w0; acc[3] += f.y * w0;
        f = __half22float2(*(__half2*)&u1.x); acc[0] += f.x * w1; acc[1] += f.y * w1;
        f = __half22float2(*(__half2*)&u1.y); acc[2] += f.x * w1; acc[3] += f.y * w1;
        f = __half22float2(*(__half2*)&u2.x); acc[0] += f.x * w2; acc[1] += f.y * w2;
        f = __half22float2(*(__half2*)&u2.y); acc[2] += f.x * w2; acc[3] += f.y * w2;
        f = __half22float2(*(__half2*)&u3.x); acc[0] += f.x * w3; acc[1] += f.y * w3;
        f = __half22float2(*(__half2*)&u3.y); acc[2] += f.x * w3; acc[3] += f.y * w3;
    }
    for (; e < r1; e++) {
        int s = g_csr[e].src;
        float2 wp = *(const float2*)&wbase[(size_t)e * 4];
        float w = hiHead ? wp.y : wp.x;
        den += w;
        uint2 u = *(const uint2*)&g_xw2h[(size_t)s * HH + col];
        float2 f;
        f = __half22float2(*(__half2*)&u.x); acc[0] += f.x * w; acc[1] += f.y * w;
        f = __half22float2(*(__half2*)&u.y); acc[2] += f.x * w; acc[3] += f.y * w;
    }
    float inv = 1.0f / den;

    float a0 = 0.0f, a1 = 0.0f;
    #pragma unroll
    for (int j = 0; j < 4; j++) {
        int c = col + j;
        float v = acc[j] * inv + sb2[c];
        v = v > 0.0f ? v : expm1f(v);
        a0 += v * sW3[c * 2];
        a1 += v * sW3[c * 2 + 1];
    }
    #pragma unroll
    for (int o = 16; o >= 1; o >>= 1) {
        a0 += __shfl_xor_sync(0xffffffffu, a0, o);
        a1 += __shfl_xor_sync(0xffffffffu, a1, o);
    }
    if (lane == 0) { sPart[wlocal][0] = a0; sPart[wlocal][1] = a1; }
    __syncthreads();
    if (tid < 4) {
        int n = blockIdx.x * 4 + tid;
        g_hw3[(size_t)n * 2]     = sPart[tid * 2][0] + sPart[tid * 2 + 1][0];
        g_hw3[(size_t)n * 2 + 1] = sPart[tid * 2][1] + sPart[tid * 2 + 1][1];
    }
}

// ---------------- GCN-2 gather ----------------------------------------------
__global__ void k_gcn2(const float* __restrict__ b3, float* __restrict__ out) {
    int warp = (blockIdx.x * blockDim.x + threadIdx.x) >> 5;
    int lane = threadIdx.x & 31;
    if (warp >= N_NODES) return;
    int r0 = g_rowptr[warp], r1 = g_rowptr[warp + 1];
    float acc0 = 0.0f, acc1 = 0.0f;
    for (int e = r0 + lane; e < r1; e += 32) {
        Edge ed = g_csr[e];
        float2 v = *(const float2*)&g_hw3[(size_t)ed.src * 2];
        acc0 += v.x * ed.norm; acc1 += v.y * ed.norm;
    }
    #pragma unroll
    for (int o = 16; o >= 1; o >>= 1) {
        acc0 += __shfl_xor_sync(0xffffffffu, acc0, o);
        acc1 += __shfl_xor_sync(0xffffffffu, acc1, o);
    }
    if (lane == 0) {
        out[(size_t)warp * 2]     = acc0 + __ldg(&b3[0]);
        out[(size_t)warp * 2 + 1] = acc1 + __ldg(&b3[1]);
    }
}

// ---------------- launch -------------------------------------------------------
extern "C" void kernel_launch(void* const* d_in, const int* in_sizes, int n_in,
                              void* d_out, int out_size) {
    const float* x    = (const float*)d_in[0];
    const int*   ei   = (const int*)d_in[1];
    const float* W1   = (const float*)d_in[2];
    const float* b1   = (const float*)d_in[3];
    const float* W2   = (const float*)d_in[4];
    const float* attS = (const float*)d_in[5];
    const float* attD = (const float*)d_in[6];
    const float* b2   = (const float*)d_in[7];
    const float* W3   = (const float*)d_in[8];
    const float* b3   = (const float*)d_in[9];
    float* out = (float*)d_out;

    const int T = 256;
    const int RB = (N_NODES + 63) / 64;
    k_init  <<<(N_NODES + T - 1) / T, T>>>();
    k_edges <<<(E2 + T - 1) / T, T>>>(ei);
    k_scan  <<<1, SCAN_T>>>();
    k_fill  <<<(E2 + T - 1) / T, T>>>(ei);
    k_gemm1 <<<RB, T>>>(x, W1);
    k_gcn1  <<<(N_NODES * 32 + T - 1) / T, T>>>(b1);
    k_gemm2 <<<dim3(RB, HEADS), T>>>(W2, attS, attD);
    k_maxred<<<(N_NODES + T - 1) / T, T>>>();
    k_weight<<<(E2 + T - 1) / T, T>>>();
    k_gat   <<<N_NODES / 4, T>>>(b2, W3);
    k_gcn2  <<<(N_NODES * 32 + T - 1) / T, T>>>(b3, out);
}

// round 11
// speedup vs baseline: 1.2017x; 1.0032x over previous
#include <cuda_runtime.h>
#include <cuda_fp16.h>
#include <math.h>

#define N_NODES 100000
#define E_EDGES 1600000
#define E2      (E_EDGES + N_NODES)   // 1,700,000
#define IN_C    128
#define HID     64
#define HEADS   4
#define HH      (HEADS * HID)         // 256
#define OUT_C   2
#define NEG_SLOPE 0.2f
#define SCAN_T  1024

struct Edge { int src; float norm; };

// ---------------- scratch ----------------------------------------------------
__device__ __align__(16) int    g_degi[N_NODES];
__device__ __align__(16) int    g_cnt[N_NODES];
__device__ __align__(16) int    g_rowptr[N_NODES + 1];
__device__ __align__(16) float  g_dinv[N_NODES];
__device__ __align__(16) Edge   g_csr[E2];
__device__ __align__(16) float4 g_w4[E2];                        // per-edge softmax weights
__device__ __align__(16) float  g_inv[(size_t)N_NODES * HEADS];  // 1/den per node/head
__device__ __align__(16) __half g_xw1h[(size_t)N_NODES * HID];
__device__ __align__(16) float  g_h0 [(size_t)N_NODES * HID];
__device__ __align__(16) __half g_xw2h[(size_t)N_NODES * HH];    // 51MB
__device__ __align__(16) float  g_as [(size_t)N_NODES * HEADS];
__device__ __align__(16) float  g_ad [(size_t)N_NODES * HEADS];
__device__ __align__(16) float  g_mx[8];
__device__ __align__(16) float  g_hw3[(size_t)N_NODES * OUT_C];

__device__ __forceinline__ float lrelu(float x) { return x > 0.0f ? x : NEG_SLOPE * x; }

__device__ __forceinline__ void atomicMaxFloat(float* addr, float value) {
    if (value >= 0.0f) atomicMax((int*)addr, __float_as_int(value));
    else               atomicMin((unsigned int*)addr, __float_as_uint(value));
}

// ---------------- CSR build --------------------------------------------------
__global__ void k_init() {
    int i = blockIdx.x * blockDim.x + threadIdx.x;
    if (i < N_NODES) { g_degi[i] = 0; g_cnt[i] = 0; }
    if (i < 8) g_mx[i] = -3.402823466e38f;
}

__global__ void k_edges(const int* __restrict__ ei) {
    int e = blockIdx.x * blockDim.x + threadIdx.x;
    if (e >= E2) return;
    int d = (e < E_EDGES) ? ei[E_EDGES + e] : (e - E_EDGES);
    atomicAdd(&g_degi[d], 1);
}

__global__ void k_scan() {
    __shared__ int part[SCAN_T];
    const int CH = (N_NODES + SCAN_T - 1) / SCAN_T;
    int t = threadIdx.x;
    int base = t * CH;
    int hi = min(base + CH, N_NODES);
    int sum = 0;
    for (int i = base; i < hi; i++) sum += g_degi[i];
    part[t] = sum;
    __syncthreads();
    for (int off = 1; off < SCAN_T; off <<= 1) {
        int v = (t >= off) ? part[t - off] : 0;
        __syncthreads();
        part[t] += v;
        __syncthreads();
    }
    int run = (t == 0) ? 0 : part[t - 1];
    for (int i = base; i < hi; i++) {
        g_rowptr[i] = run;
        int dg = g_degi[i];
        g_dinv[i] = dg > 0 ? rsqrtf((float)dg) : 0.0f;
        run += dg;
    }
    if (t == SCAN_T - 1) g_rowptr[N_NODES] = run;
}

__global__ void k_fill(const int* __restrict__ ei) {
    int e = blockIdx.x * blockDim.x + threadIdx.x;
    if (e >= E2) return;
    int s, d;
    if (e < E_EDGES) { s = ei[e]; d = ei[E_EDGES + e]; }
    else             { s = e - E_EDGES; d = s; }
    int pos = g_rowptr[d] + atomicAdd(&g_cnt[d], 1);
    Edge ed; ed.src = s; ed.norm = g_dinv[s] * g_dinv[d];
    g_csr[pos] = ed;
}

// ---------------- GEMM 1: xw1h = fp16(x @ W1)   64x64 tile, 4x4/thread -----
__global__ void __launch_bounds__(256) k_gemm1(const float* __restrict__ x,
                                               const float* __restrict__ W1) {
    __shared__ __align__(16) float As[64][68];
    __shared__ __align__(16) float Bs[64][HID];
    int tid = threadIdx.x;
    int tx = tid & 15, ty = tid >> 4;
    int row0 = blockIdx.x * 64;
    float acc[4][4];
    #pragma unroll
    for (int i = 0; i < 4; i++)
        #pragma unroll
        for (int j = 0; j < 4; j++) acc[i][j] = 0.0f;

    for (int kc = 0; kc < IN_C; kc += 64) {
        __syncthreads();
        #pragma unroll
        for (int it = 0; it < 4; it++) {
            int idx = tid + it * 256;
            int r = idx >> 4, k4 = idx & 15;
            int row = row0 + r;
            float4 v = make_float4(0.f, 0.f, 0.f, 0.f);
            if (row < N_NODES)
                v = *(const float4*)&x[(size_t)row * IN_C + kc + k4 * 4];
            *(float4*)&As[r][k4 * 4] = v;
        }
        #pragma unroll
        for (int it = 0; it < 4; it++) {
            int idx = tid + it * 256;
            int k = idx >> 4, c4 = idx & 15;
            *(float4*)&Bs[k][c4 * 4] = *(const float4*)&W1[(size_t)(kc + k) * HID + c4 * 4];
        }
        __syncthreads();
        #pragma unroll 16
        for (int k = 0; k < 64; k++) {
            float a0 = As[ty * 4 + 0][k], a1 = As[ty * 4 + 1][k];
            float a2 = As[ty * 4 + 2][k], a3 = As[ty * 4 + 3][k];
            float4 b = *(const float4*)&Bs[k][tx * 4];
            acc[0][0] += a0 * b.x; acc[0][1] += a0 * b.y; acc[0][2] += a0 * b.z; acc[0][3] += a0 * b.w;
            acc[1][0] += a1 * b.x; acc[1][1] += a1 * b.y; acc[1][2] += a1 * b.z; acc[1][3] += a1 * b.w;
            acc[2][0] += a2 * b.x; acc[2][1] += a2 * b.y; acc[2][2] += a2 * b.z; acc[2][3] += a2 * b.w;
            acc[3][0] += a3 * b.x; acc[3][1] += a3 * b.y; acc[3][2] += a3 * b.z; acc[3][3] += a3 * b.w;
        }
    }
    #pragma unroll
    for (int i = 0; i < 4; i++) {
        int row = row0 + ty * 4 + i;
        if (row < N_NODES) {
            __half2 p0 = __floats2half2_rn(acc[i][0], acc[i][1]);
            __half2 p1 = __floats2half2_rn(acc[i][2], acc[i][3]);
            uint2 u; u.x = *(unsigned*)&p0; u.y = *(unsigned*)&p1;
            *(uint2*)&g_xw1h[(size_t)row * HID + tx * 4] = u;
        }
    }
}

// ---------------- GCN-1 gather (fp16, 4-unroll) ----------------------------
__global__ void k_gcn1(const float* __restrict__ b1) {
    int warp = (blockIdx.x * blockDim.x + threadIdx.x) >> 5;
    int lane = threadIdx.x & 31;
    if (warp >= N_NODES) return;
    int r0 = g_rowptr[warp], r1 = g_rowptr[warp + 1];
    float acc0 = 0.0f, acc1 = 0.0f;
    int off = lane * 2;
    int e = r0;
    for (; e + 4 <= r1; e += 4) {
        Edge e0 = g_csr[e], e1 = g_csr[e + 1], e2 = g_csr[e + 2], e3 = g_csr[e + 3];
        __half2 h0 = *(const __half2*)&g_xw1h[(size_t)e0.src * HID + off];
        __half2 h1 = *(const __half2*)&g_xw1h[(size_t)e1.src * HID + off];
        __half2 h2 = *(const __half2*)&g_xw1h[(size_t)e2.src * HID + off];
        __half2 h3 = *(const __half2*)&g_xw1h[(size_t)e3.src * HID + off];
        float2 v0 = __half22float2(h0), v1 = __half22float2(h1);
        float2 v2 = __half22float2(h2), v3 = __half22float2(h3);
        acc0 += v0.x * e0.norm + v1.x * e1.norm + v2.x * e2.norm + v3.x * e3.norm;
        acc1 += v0.y * e0.norm + v1.y * e1.norm + v2.y * e2.norm + v3.y * e3.norm;
    }
    for (; e < r1; e++) {
        Edge ed = g_csr[e];
        float2 v = __half22float2(*(const __half2*)&g_xw1h[(size_t)ed.src * HID + off]);
        acc0 += v.x * ed.norm; acc1 += v.y * ed.norm;
    }
    float2 o;
    o.x = fmaxf(acc0 + __ldg(&b1[off]),     0.0f);
    o.y = fmaxf(acc1 + __ldg(&b1[off + 1]), 0.0f);
    *(float2*)&g_h0[(size_t)warp * HID + off] = o;
}

// ---------------- GEMM 2: xw2h = fp16(h0 @ W2), + attention dots -----------
__global__ void __launch_bounds__(256) k_gemm2(const float* __restrict__ W2,
                                               const float* __restrict__ attS,
                                               const float* __restrict__ attD) {
    __shared__ __align__(16) float As[64][68];
    __shared__ __align__(16) float Bs[64][64];
    __shared__ float sa[64], sd[64];
    int tid = threadIdx.x;
    int tx = tid & 15, ty = tid >> 4;
    int head = blockIdx.y;
    int row0 = blockIdx.x * 64;

    #pragma unroll
    for (int it = 0; it < 4; it++) {
        int idx = tid + it * 256;
        int r = idx >> 4, k4 = idx & 15;
        int row = row0 + r;
        float4 v = make_float4(0.f, 0.f, 0.f, 0.f);
        if (row < N_NODES)
            v = *(const float4*)&g_h0[(size_t)row * HID + k4 * 4];
        *(float4*)&As[r][k4 * 4] = v;
    }
    #pragma unroll
    for (int it = 0; it < 4; it++) {
        int idx = tid + it * 256;
        int k = idx >> 4, c4 = idx & 15;
        *(float4*)&Bs[k][c4 * 4] =
            *(const float4*)&W2[(size_t)k * HH + head * 64 + c4 * 4];
    }
    if (tid < 64) { sa[tid] = attS[head * 64 + tid]; sd[tid] = attD[head * 64 + tid]; }
    __syncthreads();

    float acc[4][4];
    #pragma unroll
    for (int i = 0; i < 4; i++)
        #pragma unroll
        for (int j = 0; j < 4; j++) acc[i][j] = 0.0f;

    #pragma unroll 16
    for (int k = 0; k < 64; k++) {
        float a0 = As[ty * 4 + 0][k], a1 = As[ty * 4 + 1][k];
        float a2 = As[ty * 4 + 2][k], a3 = As[ty * 4 + 3][k];
        float4 b = *(const float4*)&Bs[k][tx * 4];
        acc[0][0] += a0 * b.x; acc[0][1] += a0 * b.y; acc[0][2] += a0 * b.z; acc[0][3] += a0 * b.w;
        acc[1][0] += a1 * b.x; acc[1][1] += a1 * b.y; acc[1][2] += a1 * b.z; acc[1][3] += a1 * b.w;
        acc[2][0] += a2 * b.x; acc[2][1] += a2 * b.y; acc[2][2] += a2 * b.z; acc[2][3] += a2 * b.w;
        acc[3][0] += a3 * b.x; acc[3][1] += a3 * b.y; acc[3][2] += a3 * b.z; acc[3][3] += a3 * b.w;
    }

    #pragma unroll
    for (int i = 0; i < 4; i++) {
        int row = row0 + ty * 4 + i;
        if (row < N_NODES) {
            __half2 p0 = __floats2half2_rn(acc[i][0], acc[i][1]);
            __half2 p1 = __floats2half2_rn(acc[i][2], acc[i][3]);
            uint2 u; u.x = *(unsigned*)&p0; u.y = *(unsigned*)&p1;
            *(uint2*)&g_xw2h[(size_t)row * HH + head * 64 + tx * 4] = u;
        }
    }

    float ps[4], pd[4];
    #pragma unroll
    for (int i = 0; i < 4; i++) {
        float s = 0.f, d = 0.f;
        #pragma unroll
        for (int j = 0; j < 4; j++) {
            s += acc[i][j] * sa[tx * 4 + j];
            d += acc[i][j] * sd[tx * 4 + j];
        }
        ps[i] = s; pd[i] = d;
    }
    #pragma unroll
    for (int off = 8; off >= 1; off >>= 1) {
        #pragma unroll
        for (int i = 0; i < 4; i++) {
            ps[i] += __shfl_xor_sync(0xffffffffu, ps[i], off);
            pd[i] += __shfl_xor_sync(0xffffffffu, pd[i], off);
        }
    }
    if (tx == 0) {
        #pragma unroll
        for (int i = 0; i < 4; i++) {
            int row = row0 + ty * 4 + i;
            if (row < N_NODES) {
                g_as[(size_t)row * HEADS + head] = ps[i];
                g_ad[(size_t)row * HEADS + head] = pd[i];
            }
        }
    }
}

// ---------------- global per-head max of a_s / a_d -------------------------
__global__ void k_maxred() {
    int i = blockIdx.x * blockDim.x + threadIdx.x;
    int lane = threadIdx.x & 31;
    float4 a = make_float4(-3.4e38f, -3.4e38f, -3.4e38f, -3.4e38f);
    float4 d = a;
    if (i < N_NODES) {
        a = *(const float4*)&g_as[(size_t)i * HEADS];
        d = *(const float4*)&g_ad[(size_t)i * HEADS];
    }
    #pragma unroll
    for (int o = 16; o >= 1; o >>= 1) {
        a.x = fmaxf(a.x, __shfl_xor_sync(0xffffffffu, a.x, o));
        a.y = fmaxf(a.y, __shfl_xor_sync(0xffffffffu, a.y, o));
        a.z = fmaxf(a.z, __shfl_xor_sync(0xffffffffu, a.z, o));
        a.w = fmaxf(a.w, __shfl_xor_sync(0xffffffffu, a.w, o));
        d.x = fmaxf(d.x, __shfl_xor_sync(0xffffffffu, d.x, o));
        d.y = fmaxf(d.y, __shfl_xor_sync(0xffffffffu, d.y, o));
        d.z = fmaxf(d.z, __shfl_xor_sync(0xffffffffu, d.z, o));
        d.w = fmaxf(d.w, __shfl_xor_sync(0xffffffffu, d.w, o));
    }
    if (lane == 0) {
        atomicMaxFloat(&g_mx[0], a.x); atomicMaxFloat(&g_mx[1], a.y);
        atomicMaxFloat(&g_mx[2], a.z); atomicMaxFloat(&g_mx[3], a.w);
        atomicMaxFloat(&g_mx[4], d.x); atomicMaxFloat(&g_mx[5], d.y);
        atomicMaxFloat(&g_mx[6], d.z); atomicMaxFloat(&g_mx[7], d.w);
    }
}

// ---------------- warp-per-node softmax weights + 1/den --------------------
// dst is implicit (CSR row); a_d is a broadcast; w4 write coalesced.
__global__ void k_weight() {
    int node = (blockIdx.x * blockDim.x + threadIdx.x) >> 5;
    int lane = threadIdx.x & 31;
    if (node >= N_NODES) return;
    float C0 = lrelu(g_mx[0] + g_mx[4]);
    float C1 = lrelu(g_mx[1] + g_mx[5]);
    float C2 = lrelu(g_mx[2] + g_mx[6]);
    float C3 = lrelu(g_mx[3] + g_mx[7]);
    float4 b = *(const float4*)&g_ad[(size_t)node * HEADS];
    int r0 = g_rowptr[node], r1 = g_rowptr[node + 1];
    float d0 = 0.f, d1 = 0.f, d2 = 0.f, d3 = 0.f;
    for (int e = r0 + lane; e < r1; e += 32) {
        int s = g_csr[e].src;
        float4 a = *(const float4*)&g_as[(size_t)s * HEADS];
        float4 w;
        w.x = __expf(lrelu(a.x + b.x) - C0);
        w.y = __expf(lrelu(a.y + b.y) - C1);
        w.z = __expf(lrelu(a.z + b.z) - C2);
        w.w = __expf(lrelu(a.w + b.w) - C3);
        g_w4[e] = w;
        d0 += w.x; d1 += w.y; d2 += w.z; d3 += w.w;
    }
    #pragma unroll
    for (int o = 16; o >= 1; o >>= 1) {
        d0 += __shfl_xor_sync(0xffffffffu, d0, o);
        d1 += __shfl_xor_sync(0xffffffffu, d1, o);
        d2 += __shfl_xor_sync(0xffffffffu, d2, o);
        d3 += __shfl_xor_sync(0xffffffffu, d3, o);
    }
    if (lane == 0) {
        float4 iv;
        iv.x = 1.0f / d0; iv.y = 1.0f / d1;
        iv.z = 1.0f / d2; iv.w = 1.0f / d3;
        *(float4*)&g_inv[(size_t)node * HEADS] = iv;
    }
}

// ---------------- fused GAT: 2 warps per node, precomputed w & 1/den -------
// block = 256 = 8 warps = 4 nodes; grid = 25000 exact.
__global__ void __launch_bounds__(256) k_gat(const float* __restrict__ b2,
                                             const float* __restrict__ W3) {
    __shared__ float sW3[HH * 2];
    __shared__ float sb2[HH];
    __shared__ float sPart[8][2];
    int tid = threadIdx.x;
    sW3[tid * 2]     = W3[tid * 2];
    sW3[tid * 2 + 1] = W3[tid * 2 + 1];
    sb2[tid]         = b2[tid];
    __syncthreads();

    int wlocal = tid >> 5;                       // 0..7
    int node   = blockIdx.x * 4 + (wlocal >> 1);
    int hpart  = wlocal & 1;                     // 128-channel half
    int lane   = tid & 31;
    int r0 = g_rowptr[node], r1 = g_rowptr[node + 1];

    int col  = hpart * 128 + lane * 4;           // 4 fp16 channels per lane
    int head = col >> 6;
    bool hiHead = (lane & 16) != 0;

    float acc[4];
    #pragma unroll
    for (int j = 0; j < 4; j++) acc[j] = 0.0f;

    const float* wbase = (const float*)g_w4 + hpart * 2;
    int e = r0;
    for (; e + 4 <= r1; e += 4) {
        int s0 = g_csr[e].src,     s1 = g_csr[e + 1].src;
        int s2 = g_csr[e + 2].src, s3 = g_csr[e + 3].src;
        float2 wp0 = *(const float2*)&wbase[(size_t)(e)     * 4];
        float2 wp1 = *(const float2*)&wbase[(size_t)(e + 1) * 4];
        float2 wp2 = *(const float2*)&wbase[(size_t)(e + 2) * 4];
        float2 wp3 = *(const float2*)&wbase[(size_t)(e + 3) * 4];
        uint2 u0 = *(const uint2*)&g_xw2h[(size_t)s0 * HH + col];
        uint2 u1 = *(const uint2*)&g_xw2h[(size_t)s1 * HH + col];
        uint2 u2 = *(const uint2*)&g_xw2h[(size_t)s2 * HH + col];
        uint2 u3 = *(const uint2*)&g_xw2h[(size_t)s3 * HH + col];
        float w0 = hiHead ? wp0.y : wp0.x;
        float w1 = hiHead ? wp1.y : wp1.x;
        float w2 = hiHead ? wp2.y : wp2.x;
        float w3 = hiHead ? wp3.y : wp3.x;
        float2 f;
        f = __half22float2(*(__half2*)&u0.x); acc[0] += f.x * w0; acc[1] += f.y * w0;
        f = __half22float2(*(__half2*)&u0.y); acc[2] += f.x * w0; acc[3] += f.y * w0;
        f = __half22float2(*(__half2*)&u1.x); acc[0] += f.x * w1; acc[1] += f.y * w1;
        f = __half22float2(*(__half2*)&u1.y); acc[2] += f.x * w1; acc[3] += f.y * w1;
        f = __half22float2(*(__half2*)&u2.x); acc[0] += f.x * w2; acc[1] += f.y * w2;
        f = __half22float2(*(__half2*)&u2.y); acc[2] += f.x * w2; acc[3] += f.y * w2;
        f = __half22float2(*(__half2*)&u3.x); acc[0] += f.x * w3; acc[1] += f.y * w3;
        f = __half22float2(*(__half2*)&u3.y); acc[2] += f.x * w3; acc[3] += f.y * w3;
    }
    for (; e < r1; e++) {
        int s = g_csr[e].src;
        float2 wp = *(const float2*)&wbase[(size_t)e * 4];
        float w = hiHead ? wp.y : wp.x;
        uint2 u = *(const uint2*)&g_xw2h[(size_t)s * HH + col];
        float2 f;
        f = __half22float2(*(__half2*)&u.x); acc[0] += f.x * w; acc[1] += f.y * w;
        f = __half22float2(*(__half2*)&u.y); acc[2] += f.x * w; acc[3] += f.y * w;
    }
    float inv = g_inv[(size_t)node * HEADS + head];

    float a0 = 0.0f, a1 = 0.0f;
    #pragma unroll
    for (int j = 0; j < 4; j++) {
        int c = col + j;
        float v = acc[j] * inv + sb2[c];
        v = v > 0.0f ? v : expm1f(v);
        a0 += v * sW3[c * 2];
        a1 += v * sW3[c * 2 + 1];
    }
    #pragma unroll
    for (int o = 16; o >= 1; o >>= 1) {
        a0 += __shfl_xor_sync(0xffffffffu, a0, o);
        a1 += __shfl_xor_sync(0xffffffffu, a1, o);
    }
    if (lane == 0) { sPart[wlocal][0] = a0; sPart[wlocal][1] = a1; }
    __syncthreads();
    if (tid < 4) {
        int n = blockIdx.x * 4 + tid;
        g_hw3[(size_t)n * 2]     = sPart[tid * 2][0] + sPart[tid * 2 + 1][0];
        g_hw3[(size_t)n * 2 + 1] = sPart[tid * 2][1] + sPart[tid * 2 + 1][1];
    }
}

// ---------------- GCN-2 gather ----------------------------------------------
__global__ void k_gcn2(const float* __restrict__ b3, float* __restrict__ out) {
    int warp = (blockIdx.x * blockDim.x + threadIdx.x) >> 5;
    int lane = threadIdx.x & 31;
    if (warp >= N_NODES) return;
    int r0 = g_rowptr[warp], r1 = g_rowptr[warp + 1];
    float acc0 = 0.0f, acc1 = 0.0f;
    for (int e = r0 + lane; e < r1; e += 32) {
        Edge ed = g_csr[e];
        float2 v = *(const float2*)&g_hw3[(size_t)ed.src * 2];
        acc0 += v.x * ed.norm; acc1 += v.y * ed.norm;
    }
    #pragma unroll
    for (int o = 16; o >= 1; o >>= 1) {
        acc0 += __shfl_xor_sync(0xffffffffu, acc0, o);
        acc1 += __shfl_xor_sync(0xffffffffu, acc1, o);
    }
    if (lane == 0) {
        out[(size_t)warp * 2]     = acc0 + __ldg(&b3[0]);
        out[(size_t)warp * 2 + 1] = acc1 + __ldg(&b3[1]);
    }
}

// ---------------- launch -------------------------------------------------------
extern "C" void kernel_launch(void* const* d_in, const int* in_sizes, int n_in,
                              void* d_out, int out_size) {
    const float* x    = (const float*)d_in[0];
    const int*   ei   = (const int*)d_in[1];
    const float* W1   = (const float*)d_in[2];
    const float* b1   = (const float*)d_in[3];
    const float* W2   = (const float*)d_in[4];
    const float* attS = (const float*)d_in[5];
    const float* attD = (const float*)d_in[6];
    const float* b2   = (const float*)d_in[7];
    const float* W3   = (const float*)d_in[8];
    const float* b3   = (const float*)d_in[9];
    float* out = (float*)d_out;

    // side stream + events created once (host objects only; no device memory)
    static cudaStream_t s2 = nullptr;
    static cudaEvent_t  evFork = nullptr, evJoin = nullptr;
    if (s2 == nullptr) {
        cudaStreamCreateWithFlags(&s2, cudaStreamNonBlocking);
        cudaEventCreateWithFlags(&evFork, cudaEventDisableTiming);
        cudaEventCreateWithFlags(&evJoin, cudaEventDisableTiming);
    }

    const int T = 256;
    const int RB = (N_NODES + 63) / 64;

    // fork: gemm1 (depends only on x,W1) overlaps the CSR build
    cudaEventRecord(evFork, 0);
    cudaStreamWaitEvent(s2, evFork, 0);
    k_gemm1 <<<RB, T, 0, s2>>>(x, W1);
    cudaEventRecord(evJoin, s2);

    k_init  <<<(N_NODES + T - 1) / T, T>>>();
    k_edges <<<(E2 + T - 1) / T, T>>>(ei);
    k_scan  <<<1, SCAN_T>>>();
    k_fill  <<<(E2 + T - 1) / T, T>>>(ei);

    // join: gcn1 needs both CSR and xw1h
    cudaStreamWaitEvent(0, evJoin, 0);

    k_gcn1  <<<(N_NODES * 32 + T - 1) / T, T>>>(b1);
    k_gemm2 <<<dim3(RB, HEADS), T>>>(W2, attS, attD);
    k_maxred<<<(N_NODES + T - 1) / T, T>>>();
    k_weight<<<(N_NODES * 32 + T - 1) / T, T>>>();
    k_gat   <<<N_NODES / 4, T>>>(b2, W3);
    k_gcn2  <<<(N_NODES * 32 + T - 1) / T, T>>>(b3, out);
}